// round 13
// baseline (speedup 1.0000x reference)
#include <cuda_runtime.h>

// ============================================================
// CQattn: S = C.w1 + Q.w2 + (C*w3)Q^T ; P1=softmax_m, P2=softmax_n
// A = P1 Q ; T = P2^T C ; Bout = P1 T.   Output = [A | Bout].
// B=32, N=2048, M=512, D=512, fp32.
// ============================================================

#define BB 32
#define NN 2048
#define MM 512
#define DD 512
#define NEGV (-1e30f)

typedef unsigned long long ull;

// ---------------- scratch (device globals; no runtime alloc) ----------------
__device__ __align__(256) float g_S [(size_t)BB*NN*MM];  // raw S, overwritten with P2
__device__ __align__(256) float g_P1[(size_t)BB*NN*MM];  // row-softmax of S
__device__ __align__(256) float g_T [(size_t)BB*MM*DD];
__device__ __align__(256) float g_Q3[(size_t)BB*MM*DD];  // Q * w3
__device__ __align__(256) float g_cw[BB*NN];             // C . w1
__device__ __align__(256) float g_qw[BB*MM];             // Q . w2

// ---------------- f32x2 packed-FMA helpers ----------------
__device__ __forceinline__ ull pack2(float x, float y){
    ull r; asm("mov.b64 %0, {%1, %2};" : "=l"(r) : "f"(x), "f"(y)); return r;
}
__device__ __forceinline__ float2 unpk(ull v){
    float2 r; asm("mov.b64 {%0, %1}, %2;" : "=f"(r.x), "=f"(r.y) : "l"(v)); return r;
}
__device__ __forceinline__ void fma2(ull &d, ull a, ull b){
    asm("fma.rn.f32x2 %0, %1, %2, %0;" : "+l"(d) : "l"(a), "l"(b));
}

// ---------------- prep: cw, qw, Q3 ----------------
__global__ void prep_c_k(const float* __restrict__ C, const float* __restrict__ w){
    int row  = blockIdx.x*8 + (threadIdx.x >> 5);
    int lane = threadIdx.x & 31;
    const float4* c4 = (const float4*)(C + (size_t)row*DD);
    const float4* w4 = (const float4*)w;
    float s = 0.f;
#pragma unroll
    for (int i = 0; i < 4; i++){
        float4 v = c4[lane + 32*i];
        float4 a = w4[lane + 32*i];
        s += v.x*a.x + v.y*a.y + v.z*a.z + v.w*a.w;
    }
#pragma unroll
    for (int o = 16; o; o >>= 1) s += __shfl_xor_sync(0xffffffffu, s, o);
    if (lane == 0) g_cw[row] = s;
}

__global__ void prep_q_k(const float* __restrict__ Q, const float* __restrict__ w){
    int row  = blockIdx.x*8 + (threadIdx.x >> 5);
    int lane = threadIdx.x & 31;
    const float4* q4 = (const float4*)(Q + (size_t)row*DD);
    float4*       o4 = (float4*)(g_Q3 + (size_t)row*DD);
    const float4* w4 = (const float4*)w;
    float s = 0.f;
#pragma unroll
    for (int i = 0; i < 4; i++){
        int idx = lane + 32*i;
        float4 v  = q4[idx];
        float4 a  = w4[128 + idx];   // w2
        float4 b3 = w4[256 + idx];   // w3
        s += v.x*a.x + v.y*a.y + v.z*a.z + v.w*a.w;
        o4[idx] = make_float4(v.x*b3.x, v.y*b3.y, v.z*b3.z, v.w*b3.w);
    }
#pragma unroll
    for (int o = 16; o; o >>= 1) s += __shfl_xor_sync(0xffffffffu, s, o);
    if (lane == 0) g_qw[row] = s;
}

// ---------------- shared GEMM compute core (128x128 tile, 8x8/thread, KT=16) ----------------
#define ROWF(i, av) { ull ap = pack2((av),(av));                              \
    fma2(acc[i][0], ap, bp0); fma2(acc[i][1], ap, bp1);                       \
    fma2(acc[i][2], ap, bp2); fma2(acc[i][3], ap, bp3); }

__device__ __forceinline__ void compute16(const float (&As)[16][132],
                                          const float (&Bs)[16][132],
                                          ull (&acc)[8][4], int tx, int ty){
#pragma unroll
    for (int k = 0; k < 16; k++){
        float4  a0  = *(const float4*)(&As[k][ty*4]);
        float4  a1  = *(const float4*)(&As[k][64 + ty*4]);
        double2 bq0 = *(const double2*)(&Bs[k][tx*4]);
        double2 bq1 = *(const double2*)(&Bs[k][64 + tx*4]);
        ull bp0 = __double_as_longlong(bq0.x), bp1 = __double_as_longlong(bq0.y);
        ull bp2 = __double_as_longlong(bq1.x), bp3 = __double_as_longlong(bq1.y);
        ROWF(0, a0.x) ROWF(1, a0.y) ROWF(2, a0.z) ROWF(3, a0.w)
        ROWF(4, a1.x) ROWF(5, a1.y) ROWF(6, a1.z) ROWF(7, a1.w)
    }
}

__device__ __forceinline__ void store_rows(float* __restrict__ base, int ld,
                                           ull (&acc)[8][4], int tx, int ty){
#pragma unroll
    for (int i = 0; i < 8; i++){
        int row = (i < 4) ? (ty*4 + i) : (64 + ty*4 + i - 4);
        float2 p0 = unpk(acc[i][0]), p1 = unpk(acc[i][1]);
        float2 p2 = unpk(acc[i][2]), p3 = unpk(acc[i][3]);
        *(float4*)(base + (size_t)row*ld + tx*4)      = make_float4(p0.x, p0.y, p1.x, p1.y);
        *(float4*)(base + (size_t)row*ld + 64 + tx*4) = make_float4(p2.x, p2.y, p3.x, p3.y);
    }
}

// ---------------- GEMM 1: S = C @ Q3^T + cw + qw (NT) ----------------
__global__ void __launch_bounds__(256, 2) gemm_S_k(const float* __restrict__ C){
    __shared__ __align__(16) float As[16][132];
    __shared__ __align__(16) float Bs[16][132];
    const int tid = threadIdx.x;
    const int tx = tid & 15, ty = tid >> 4;
    const int b = blockIdx.z;
    const int m0 = blockIdx.x*128, n0 = blockIdx.y*128;
    const float* Ap = C    + ((size_t)b*NN + n0)*DD;
    const float* Bp = g_Q3 + ((size_t)b*MM + m0)*DD;
    const int lr = tid >> 1, lk = (tid & 1)*4;

    ull acc[8][4];
#pragma unroll
    for (int i = 0; i < 8; i++)
#pragma unroll
        for (int j = 0; j < 4; j++) acc[i][j] = 0ull;

    const float* ag = Ap + (size_t)lr*DD + lk;
    const float* bg = Bp + (size_t)lr*DD + lk;
    float4 av0 = *(const float4*)(ag);
    float4 av1 = *(const float4*)(ag + 8);
    float4 bv0 = *(const float4*)(bg);
    float4 bv1 = *(const float4*)(bg + 8);

    for (int kt = 0; kt < DD; kt += 16){
        __syncthreads();
        As[lk+0][lr]=av0.x; As[lk+1][lr]=av0.y; As[lk+2][lr]=av0.z; As[lk+3][lr]=av0.w;
        As[lk+8][lr]=av1.x; As[lk+9][lr]=av1.y; As[lk+10][lr]=av1.z; As[lk+11][lr]=av1.w;
        Bs[lk+0][lr]=bv0.x; Bs[lk+1][lr]=bv0.y; Bs[lk+2][lr]=bv0.z; Bs[lk+3][lr]=bv0.w;
        Bs[lk+8][lr]=bv1.x; Bs[lk+9][lr]=bv1.y; Bs[lk+10][lr]=bv1.z; Bs[lk+11][lr]=bv1.w;
        __syncthreads();
        if (kt + 16 < DD){
            av0 = *(const float4*)(ag + kt + 16);
            av1 = *(const float4*)(ag + kt + 24);
            bv0 = *(const float4*)(bg + kt + 16);
            bv1 = *(const float4*)(bg + kt + 24);
        }
        compute16(As, Bs, acc, tx, ty);
    }

    float* Sb = g_S + ((size_t)b*NN + n0)*MM + m0;
    float q0[4], q1[4];
#pragma unroll
    for (int j = 0; j < 4; j++){
        q0[j] = g_qw[b*MM + m0 + tx*4 + j];
        q1[j] = g_qw[b*MM + m0 + 64 + tx*4 + j];
    }
#pragma unroll
    for (int i = 0; i < 8; i++){
        int row = (i < 4) ? (ty*4 + i) : (64 + ty*4 + i - 4);
        float ca = g_cw[b*NN + n0 + row];
        float2 p0 = unpk(acc[i][0]), p1 = unpk(acc[i][1]);
        float2 p2 = unpk(acc[i][2]), p3 = unpk(acc[i][3]);
        *(float4*)(Sb + (size_t)row*MM + tx*4) =
            make_float4(p0.x+ca+q0[0], p0.y+ca+q0[1], p1.x+ca+q0[2], p1.y+ca+q0[3]);
        *(float4*)(Sb + (size_t)row*MM + 64 + tx*4) =
            make_float4(p2.x+ca+q1[0], p2.y+ca+q1[1], p3.x+ca+q1[2], p3.y+ca+q1[3]);
    }
}

// ---------------- row softmax (axis m, Qmask) -> P1 ----------------
__global__ void row_softmax_k(const int* __restrict__ Qmask){
    int gw   = blockIdx.x*8 + (threadIdx.x >> 5);   // global row in [0, B*N)
    int lane = threadIdx.x & 31;
    int b    = gw >> 11;                            // / 2048
    const float4* Sr = (const float4*)(g_S  + (size_t)gw*MM);
    float4*       Pr = (float4*)      (g_P1 + (size_t)gw*MM);
    const int4*   qm = (const int4*)(Qmask + b*MM);
    float v[16];
    float mx = -3.4e38f;
#pragma unroll
    for (int i = 0; i < 4; i++){
        float4 s = Sr[lane + 32*i];
        int4   q = qm[lane + 32*i];
        float v0 = q.x ? NEGV : s.x;
        float v1 = q.y ? NEGV : s.y;
        float v2 = q.z ? NEGV : s.z;
        float v3 = q.w ? NEGV : s.w;
        v[4*i]=v0; v[4*i+1]=v1; v[4*i+2]=v2; v[4*i+3]=v3;
        mx = fmaxf(mx, fmaxf(fmaxf(v0, v1), fmaxf(v2, v3)));
    }
#pragma unroll
    for (int o = 16; o; o >>= 1) mx = fmaxf(mx, __shfl_xor_sync(0xffffffffu, mx, o));
    float sm = 0.f;
#pragma unroll
    for (int i = 0; i < 16; i++){ v[i] = __expf(v[i] - mx); sm += v[i]; }
#pragma unroll
    for (int o = 16; o; o >>= 1) sm += __shfl_xor_sync(0xffffffffu, sm, o);
    float inv = 1.0f / sm;
#pragma unroll
    for (int i = 0; i < 4; i++)
        Pr[lane + 32*i] = make_float4(v[4*i]*inv, v[4*i+1]*inv, v[4*i+2]*inv, v[4*i+3]*inv);
}

// ---------------- column softmax (axis n, Cmask), in-place S -> P2 ----------------
__global__ void col_softmax_k(const int* __restrict__ Cmask){
    int b  = blockIdx.y;
    int mi = threadIdx.x & 31;
    int m  = blockIdx.x*32 + mi;
    int h  = threadIdx.x >> 5;                 // 0..7 n-slices
    float* Sb = g_S + (size_t)b*NN*MM;
    const int* cm = Cmask + b*NN;

    float mx = -3.4e38f, sm = 0.f;
    for (int n = h; n < NN; n += 8){
        float v  = cm[n] ? NEGV : Sb[(size_t)n*MM + m];
        float nm = fmaxf(mx, v);
        sm = sm*__expf(mx - nm) + __expf(v - nm);
        mx = nm;
    }
    __shared__ float smx[8][32], ssm[8][32];
    smx[h][mi] = mx; ssm[h][mi] = sm;
    __syncthreads();
    float M2 = -3.4e38f;
#pragma unroll
    for (int j = 0; j < 8; j++) M2 = fmaxf(M2, smx[j][mi]);
    float S2 = 0.f;
#pragma unroll
    for (int j = 0; j < 8; j++) S2 += ssm[j][mi]*__expf(smx[j][mi] - M2);
    float inv = 1.0f / S2;
    for (int n = h; n < NN; n += 8){
        size_t idx = (size_t)n*MM + m;
        float v = cm[n] ? NEGV : Sb[idx];
        Sb[idx] = __expf(v - M2)*inv;
    }
}

// ---------------- GEMM 2: T = P2^T @ C (TN, K = N = 2048) ----------------
__global__ void __launch_bounds__(256, 2) gemm_T_k(const float* __restrict__ C){
    __shared__ __align__(16) float As[16][132];
    __shared__ __align__(16) float Bs[16][132];
    const int tid = threadIdx.x;
    const int tx = tid & 15, ty = tid >> 4;
    const int b = blockIdx.z;
    const int d0 = blockIdx.x*128, m0 = blockIdx.y*128;
    const float* Ap = g_S + (size_t)b*NN*MM + m0;   // (n, m) k-rows
    const float* Bp = C   + (size_t)b*NN*DD + d0;   // (n, d) k-rows
    const int kr = tid >> 5, c = (tid & 31)*4;

    ull acc[8][4];
#pragma unroll
    for (int i = 0; i < 8; i++)
#pragma unroll
        for (int j = 0; j < 4; j++) acc[i][j] = 0ull;

    const float* ag = Ap + (size_t)kr*MM + c;
    const float* bg = Bp + (size_t)kr*DD + c;
    float4 av0 = *(const float4*)(ag);
    float4 av1 = *(const float4*)(ag + (size_t)8*MM);
    float4 bv0 = *(const float4*)(bg);
    float4 bv1 = *(const float4*)(bg + (size_t)8*DD);

    for (int kt = 0; kt < NN; kt += 16){
        __syncthreads();
        *(float4*)&As[kr  ][c] = av0;  *(float4*)&As[kr+8][c] = av1;
        *(float4*)&Bs[kr  ][c] = bv0;  *(float4*)&Bs[kr+8][c] = bv1;
        __syncthreads();
        if (kt + 16 < NN){
            av0 = *(const float4*)(ag + (size_t)(kt+16)*MM);
            av1 = *(const float4*)(ag + (size_t)(kt+24)*MM);
            bv0 = *(const float4*)(bg + (size_t)(kt+16)*DD);
            bv1 = *(const float4*)(bg + (size_t)(kt+24)*DD);
        }
        compute16(As, Bs, acc, tx, ty);
    }
    float* Tb = g_T + ((size_t)b*MM + m0)*DD + d0;
    store_rows(Tb, DD, acc, tx, ty);
}

// ---------------- GEMM 3/4: Out = P1 @ W (NN), W = Q (A) or g_T (Bout) ----------------
__global__ void __launch_bounds__(256, 2) gemm_NN_k(const float* __restrict__ Wext,
                                                    int useT, float* __restrict__ Out){
    __shared__ __align__(16) float As[16][132];
    __shared__ __align__(16) float Bs[16][132];
    const int tid = threadIdx.x;
    const int tx = tid & 15, ty = tid >> 4;
    const int b = blockIdx.z;
    const int d0 = blockIdx.x*128, n0 = blockIdx.y*128;
    const float* Ap = g_P1 + ((size_t)b*NN + n0)*MM;               // (n, m) k-contig
    const float* Bp = (useT ? (const float*)g_T : Wext) + (size_t)b*MM*DD + d0;  // (m, d)
    const int lr = tid >> 1, lk = (tid & 1)*4;     // A transpose-load
    const int kr = tid >> 5, c  = (tid & 31)*4;    // B direct-load

    ull acc[8][4];
#pragma unroll
    for (int i = 0; i < 8; i++)
#pragma unroll
        for (int j = 0; j < 4; j++) acc[i][j] = 0ull;

    const float* ag = Ap + (size_t)lr*MM + lk;
    const float* bg = Bp + (size_t)kr*DD + c;
    float4 av0 = *(const float4*)(ag);
    float4 av1 = *(const float4*)(ag + 8);
    float4 bv0 = *(const float4*)(bg);
    float4 bv1 = *(const float4*)(bg + (size_t)8*DD);

    for (int kt = 0; kt < MM; kt += 16){
        __syncthreads();
        As[lk+0][lr]=av0.x; As[lk+1][lr]=av0.y; As[lk+2][lr]=av0.z; As[lk+3][lr]=av0.w;
        As[lk+8][lr]=av1.x; As[lk+9][lr]=av1.y; As[lk+10][lr]=av1.z; As[lk+11][lr]=av1.w;
        *(float4*)&Bs[kr  ][c] = bv0;  *(float4*)&Bs[kr+8][c] = bv1;
        __syncthreads();
        if (kt + 16 < MM){
            av0 = *(const float4*)(ag + kt + 16);
            av1 = *(const float4*)(ag + kt + 24);
            bv0 = *(const float4*)(bg + (size_t)(kt+16)*DD);
            bv1 = *(const float4*)(bg + (size_t)(kt+24)*DD);
        }
        compute16(As, Bs, acc, tx, ty);
    }
    float* Ob = Out + ((size_t)b*NN + n0)*DD + d0;
    store_rows(Ob, DD, acc, tx, ty);
}

// ---------------- launch ----------------
extern "C" void kernel_launch(void* const* d_in, const int* in_sizes, int n_in,
                              void* d_out, int out_size){
    (void)in_sizes; (void)n_in; (void)out_size;
    const float* C     = (const float*)d_in[0];
    const float* Q     = (const float*)d_in[1];
    const int*   Cmask = (const int*)d_in[2];
    const int*   Qmask = (const int*)d_in[3];
    const float* w     = (const float*)d_in[4];
    float* out = (float*)d_out;

    prep_c_k<<<(BB*NN)/8, 256>>>(C, w);
    prep_q_k<<<(BB*MM)/8, 256>>>(Q, w);
    gemm_S_k<<<dim3(MM/128, NN/128, BB), 256>>>(C);
    row_softmax_k<<<(BB*NN)/8, 256>>>(Qmask);
    col_softmax_k<<<dim3(MM/32, BB), 256>>>(Cmask);
    gemm_T_k<<<dim3(DD/128, MM/128, BB), 256>>>(C);
    gemm_NN_k<<<dim3(DD/128, NN/128, BB), 256>>>(Q, 0, out);                      // A
    gemm_NN_k<<<dim3(DD/128, NN/128, BB), 256>>>(Q, 1, out + (size_t)BB*NN*DD);   // Bout
}